// round 17
// baseline (speedup 1.0000x reference)
#include <cuda_runtime.h>
#include <cuda_bf16.h>
#include <cstdint>

// ---------------- problem constants ----------------
#define N_STREAMS 8
#define D_MODEL   2048
#define NS        16
#define N_SKEW    120
#define KPAD      128
#define TOKENS    8192

#define TILE_M    16
#define N_TILES   (TOKENS / TILE_M)    // 512
#define GRID      296                  // 2 x 148 SMs
#define KC        64                   // d per chunk
#define NC        (D_MODEL / KC)       // 32 chunks
#define PITCH_B   144                  // row pitch bytes (72 bf16)

#define THREADS   256

// smem layout (bytes)
#define A_OFF(buf, hl) (((buf) * 2 + (hl)) * 2304)           // 16 rows * 144
#define B_BASE 9216
#define B_OFF(buf, hl) (B_BASE + ((buf) * 2 + (hl)) * 18432) // 128 rows * 144
#define BIAS_OFF (B_BASE + 73728)                            // 82944
#define CTR_OFF  (BIAS_OFF + 512)                            // 83456
#define SMEM_TOTAL (CTR_OFF + 16)                            // 83472; x2 < 228K

// named barriers: FULL[b] = 1+b, EMPTY[b] = 3+b
#define BAR_SYNC(id)   asm volatile("bar.sync %0, 256;"   :: "r"(id) : "memory")
#define BAR_ARRIVE(id) asm volatile("bar.arrive %0, 256;" :: "r"(id) : "memory")

// ---------------- device scratch ----------------
__device__ __nv_bfloat16 g_Whi[KPAD * D_MODEL];   // 512 KB
__device__ __nv_bfloat16 g_Wlo[KPAD * D_MODEL];   // 512 KB
__device__ int g_tile_ctr;

// ---------------- K0: W -> bf16 hi/lo; reset tile counter ----------------
__global__ void prep_wt_kernel(const float* __restrict__ W) {
    int id = blockIdx.x * 256 + threadIdx.x;
    if (id == 0) g_tile_ctr = GRID;               // tiles 0..GRID-1 pre-assigned
    int k = id >> 11, d = id & (D_MODEL - 1);
    float v = (k < N_SKEW) ? W[k * D_MODEL + d] : 0.f;
    __nv_bfloat16 hi = __float2bfloat16(v);
    __nv_bfloat16 lo = __float2bfloat16(v - __bfloat162float(hi));
    g_Whi[id] = hi;
    g_Wlo[id] = lo;
}

// ---------------- fused kernel ----------------
__device__ __forceinline__ void mma16816(float c[4], const uint32_t a[4],
                                         uint32_t b0, uint32_t b1) {
    asm volatile(
        "mma.sync.aligned.m16n8k16.row.col.f32.bf16.bf16.f32 "
        "{%0,%1,%2,%3}, {%4,%5,%6,%7}, {%8,%9}, {%0,%1,%2,%3};"
        : "+f"(c[0]), "+f"(c[1]), "+f"(c[2]), "+f"(c[3])
        : "r"(a[0]), "r"(a[1]), "r"(a[2]), "r"(a[3]), "r"(b0), "r"(b1));
}

// producer: stage one chunk (A: 16 tokens, B: 128 rows) into buffer buf
__device__ __forceinline__ void produce_chunk(
    char* smem, const float* __restrict__ streams,
    int tok0, int d0, int buf, int ptid) {
    // A: 16 tok x 16 slots = 256 items; 2 per thread, 16 LDG.128 in flight
    {
        int idx0  = ptid;
        int idx1  = ptid + 128;
        int tk0i  = idx0 >> 4, sl0 = idx0 & 15;
        int tk1i  = idx1 >> 4, sl1 = idx1 & 15;
        const float4* s0 = reinterpret_cast<const float4*>(streams)
            + ((size_t)(tok0 + tk0i) * N_STREAMS * D_MODEL + d0) / 4 + sl0;
        const float4* s1 = reinterpret_cast<const float4*>(streams)
            + ((size_t)(tok0 + tk1i) * N_STREAMS * D_MODEL + d0) / 4 + sl1;
        float4 v[N_STREAMS], u[N_STREAMS];
        #pragma unroll
        for (int n = 0; n < N_STREAMS; n++) {
            v[n] = s0[n * (D_MODEL / 4)];
            u[n] = s1[n * (D_MODEL / 4)];
        }
        #pragma unroll
        for (int s = N_STREAMS / 2; s > 0; s >>= 1)
            #pragma unroll
            for (int n = 0; n < s; n++) {
                v[n].x += v[n+s].x; v[n].y += v[n+s].y;
                v[n].z += v[n+s].z; v[n].w += v[n+s].w;
                u[n].x += u[n+s].x; u[n].y += u[n+s].y;
                u[n].z += u[n+s].z; u[n].w += u[n+s].w;
            }
        float f0[4] = { v[0].x*0.125f, v[0].y*0.125f, v[0].z*0.125f, v[0].w*0.125f };
        float f1[4] = { u[0].x*0.125f, u[0].y*0.125f, u[0].z*0.125f, u[0].w*0.125f };
        __nv_bfloat16 h0[4], l0[4], h1[4], l1[4];
        #pragma unroll
        for (int i = 0; i < 4; i++) {
            h0[i] = __float2bfloat16(f0[i]);
            l0[i] = __float2bfloat16(f0[i] - __bfloat162float(h0[i]));
            h1[i] = __float2bfloat16(f1[i]);
            l1[i] = __float2bfloat16(f1[i] - __bfloat162float(h1[i]));
        }
        *reinterpret_cast<uint2*>(smem + A_OFF(buf,0) + tk0i * PITCH_B + sl0 * 8) =
            *reinterpret_cast<uint2*>(h0);
        *reinterpret_cast<uint2*>(smem + A_OFF(buf,1) + tk0i * PITCH_B + sl0 * 8) =
            *reinterpret_cast<uint2*>(l0);
        *reinterpret_cast<uint2*>(smem + A_OFF(buf,0) + tk1i * PITCH_B + sl1 * 8) =
            *reinterpret_cast<uint2*>(h1);
        *reinterpret_cast<uint2*>(smem + A_OFF(buf,1) + tk1i * PITCH_B + sl1 * 8) =
            *reinterpret_cast<uint2*>(l1);
    }
    // B: 128 rows x 8 quads = 1024; 8 per thread (hi+lo, L2-resident)
    #pragma unroll
    for (int p = 0; p < 8; p++) {
        int idx = ptid + p * 128;
        int r = idx >> 3, q = idx & 7;
        size_t gsrc = (size_t)r * D_MODEL + d0 + q * 8;
        *reinterpret_cast<uint4*>(smem + B_OFF(buf,0) + r * PITCH_B + q * 16) =
            *reinterpret_cast<const uint4*>(&g_Whi[gsrc]);
        *reinterpret_cast<uint4*>(smem + B_OFF(buf,1) + r * PITCH_B + q * 16) =
            *reinterpret_cast<const uint4*>(&g_Wlo[gsrc]);
    }
}

__global__ void __launch_bounds__(THREADS, 2)
gomhc_fused_kernel(const float* __restrict__ streams,
                   const float* __restrict__ bias,
                   float* __restrict__ out) {
    extern __shared__ char smem[];
    const int tid  = threadIdx.x;
    const int wid  = tid >> 5;
    const int lane = tid & 31;

    if (tid < KPAD)
        *reinterpret_cast<float*>(smem + BIAS_OFF + tid * 4) =
            (tid < N_SKEW) ? bias[tid] : 0.f;

    const bool producer = (wid >= 4);
    const int g  = lane >> 2;
    const int t  = lane & 3;
    const int wn = (wid & 3) * 32;

    int tile = blockIdx.x;
    __syncthreads();   // bias staged; also orders first use of CTR_OFF

    #pragma unroll 1
    while (tile < N_TILES) {
        const int tok0 = tile * TILE_M;

        if (producer) {
            const int ptid = tid - 128;
            produce_chunk(smem, streams, tok0, 0 * KC, 0, ptid);
            BAR_ARRIVE(1);
            produce_chunk(smem, streams, tok0, 1 * KC, 1, ptid);
            BAR_ARRIVE(2);
            #pragma unroll 1
            for (int c = 2; c < NC; c++) {
                BAR_SYNC(3 + (c & 1));                 // EMPTY
                produce_chunk(smem, streams, tok0, c * KC, c & 1, ptid);
                BAR_ARRIVE(1 + (c & 1));               // FULL
            }
            __syncthreads();                           // join consumers
        } else {
            float acc[4][4];
            #pragma unroll
            for (int nt = 0; nt < 4; nt++)
                #pragma unroll
                for (int i = 0; i < 4; i++) acc[nt][i] = 0.f;

            #pragma unroll 1
            for (int c = 0; c < NC; c++) {
                const int buf = c & 1;
                BAR_SYNC(1 + buf);                     // FULL
                const char* pah = smem + A_OFF(buf, 0);
                const char* pal = smem + A_OFF(buf, 1);
                const char* pbh = smem + B_OFF(buf, 0);
                const char* pbl = smem + B_OFF(buf, 1);
                #pragma unroll
                for (int ks = 0; ks < 4; ks++) {
                    const int kb = ks * 16 + 2 * t;
                    uint32_t Ah[4], Al[4];
                    Ah[0] = *reinterpret_cast<const uint32_t*>(pah + (g    ) * PITCH_B + kb * 2);
                    Ah[1] = *reinterpret_cast<const uint32_t*>(pah + (g + 8) * PITCH_B + kb * 2);
                    Ah[2] = *reinterpret_cast<const uint32_t*>(pah + (g    ) * PITCH_B + (kb + 8) * 2);
                    Ah[3] = *reinterpret_cast<const uint32_t*>(pah + (g + 8) * PITCH_B + (kb + 8) * 2);
                    Al[0] = *reinterpret_cast<const uint32_t*>(pal + (g    ) * PITCH_B + kb * 2);
                    Al[1] = *reinterpret_cast<const uint32_t*>(pal + (g + 8) * PITCH_B + kb * 2);
                    Al[2] = *reinterpret_cast<const uint32_t*>(pal + (g    ) * PITCH_B + (kb + 8) * 2);
                    Al[3] = *reinterpret_cast<const uint32_t*>(pal + (g + 8) * PITCH_B + (kb + 8) * 2);
                    #pragma unroll
                    for (int nt = 0; nt < 4; nt++) {
                        int n0 = wn + nt * 8 + g;
                        uint32_t bh0 = *reinterpret_cast<const uint32_t*>(pbh + n0 * PITCH_B + kb * 2);
                        uint32_t bh1 = *reinterpret_cast<const uint32_t*>(pbh + n0 * PITCH_B + (kb + 8) * 2);
                        uint32_t bl0 = *reinterpret_cast<const uint32_t*>(pbl + n0 * PITCH_B + kb * 2);
                        uint32_t bl1 = *reinterpret_cast<const uint32_t*>(pbl + n0 * PITCH_B + (kb + 8) * 2);
                        mma16816(acc[nt], Ah, bh0, bh1);
                        mma16816(acc[nt], Ah, bl0, bl1);
                        mma16816(acc[nt], Al, bh0, bh1);
                    }
                }
                // skip EMPTY arrive for the last two chunks so arrive/sync
                // counts pair exactly within each tile (no stale carryover)
                if (c + 2 < NC) BAR_ARRIVE(3 + buf);
            }
            __syncthreads();                           // join producers

            // z -> smem (alias over A region, 8 KB)
            float* zs = reinterpret_cast<float*>(smem);
            #pragma unroll
            for (int nt = 0; nt < 4; nt++) {
                int col = wn + nt * 8 + 2 * t;
                *reinterpret_cast<float2*>(&zs[g * KPAD + col]) =
                    make_float2(acc[nt][0], acc[nt][1]);
                *reinterpret_cast<float2*>(&zs[(g + 8) * KPAD + col]) =
                    make_float2(acc[nt][2], acc[nt][3]);
            }
        }

        // grab next tile while z lands
        if (tid == 0)
            *reinterpret_cast<int*>(smem + CTR_OFF) = atomicAdd(&g_tile_ctr, 1);
        __syncthreads();                               // zs + next-tile visible

        // ---- solve: 8 warps x 2 tokens = 16 ----
        {
            float* zs = reinterpret_cast<float*>(smem);
            const float* bs = reinterpret_cast<const float*>(smem + BIAS_OFF);
            const int half = lane >> 4;
            const int r    = lane & 15;
            const unsigned mask = 0xffffffffu;
            const int tk = wid * 2 + half;             // 0..15
            const float* zt = zs + tk * KPAD;

            float m[32];
            #pragma unroll
            for (int cc = 0; cc < NS; cc++) {
                float a = 0.f;
                if (cc > r) {
                    int u = (r * (31 - r)) / 2 + (cc - r - 1);
                    a = zt[u] + bs[u];
                } else if (cc < r) {
                    int u = (cc * (31 - cc)) / 2 + (r - cc - 1);
                    a = -(zt[u] + bs[u]);
                }
                float diag = (cc == r) ? 1.f : 0.f;
                m[cc]      = diag + a;
                m[16 + cc] = diag - a;
            }
            #pragma unroll
            for (int i = 0; i < NS; i++) {
                const int src = i + (half << 4);
                float pivi = __shfl_sync(mask, m[i], src);
                float rp = 1.0f / pivi;
                float cf = (r == i) ? (1.0f - rp) : m[i] * rp;
                #pragma unroll
                for (int k = 0; k < 32; k++) {
                    float pk = __shfl_sync(mask, m[k], src);
                    m[k] = fmaf(-cf, pk, m[k]);
                }
            }
            float hq[8];
            #pragma unroll
            for (int q = 0; q < 8; q++) {
                float q0 = m[16 + 2 * q], q1 = m[16 + 2 * q + 1];
                hq[q] = q0 * q0 + q1 * q1;
            }
            #pragma unroll
            for (int q = 0; q < 8; q++)
                hq[q] += __shfl_xor_sync(mask, hq[q], 1);

            if (!(r & 1)) {
                const int tok = tok0 + tk;
                float* o = out + (size_t)tok * 64 + (r >> 1) * 8;
                #pragma unroll
                for (int q = 0; q < 8; q++) o[q] = 0.5f * hq[q];
            }
        }

        int next = *reinterpret_cast<const int*>(smem + CTR_OFF);
        __syncthreads();   // solve reads of zs done before next tile overwrites A
        tile = next;
    }
}

// ---------------- launch ----------------
extern "C" void kernel_launch(void* const* d_in, const int* in_sizes, int n_in,
                              void* d_out, int out_size) {
    const float* streams = (const float*)d_in[0];
    const float* W       = (const float*)d_in[1];
    const float* b       = (const float*)d_in[2];
    float* out = (float*)d_out;

    prep_wt_kernel<<<(KPAD * D_MODEL) / 256, 256>>>(W);

    cudaFuncSetAttribute(gomhc_fused_kernel,
                         cudaFuncAttributeMaxDynamicSharedMemorySize, SMEM_TOTAL);
    gomhc_fused_kernel<<<GRID, THREADS, SMEM_TOTAL>>>(streams, b, out);
}